// round 8
// baseline (speedup 1.0000x reference)
#include <cuda_runtime.h>
#include <cuda_bf16.h>
#include <cstdint>
#include <cstddef>

// ===================== problem dims =====================
static constexpr int BATCH = 16384;
static constexpr int IN_F  = 2048;
static constexpr int OUT_F = 2048;

// C = A_hi*W_hi (bf16)  +  2^-19 * ( [A_lo*2^14 | A_hi*2^5] . [W_hi*2^5 ; W_lo*2^14] ) (int8, K=4096)

// ===================== device scratch =====================
__device__ __nv_bfloat16 g_Abf[(size_t)BATCH * IN_F];      // 64 MiB  A_hi bf16
__device__ uint8_t       g_A8 [(size_t)BATCH * 2 * IN_F];  // 64 MiB  [A_lo8 | A_hi8]
__device__ __nv_bfloat16 g_Wbf[(size_t)OUT_F * IN_F];      //  8 MiB  W_hi bf16
__device__ uint8_t       g_W8 [(size_t)OUT_F * 2 * IN_F];  //  8 MiB  [W_hi8 | W_lo8]

// ===================== helpers =====================
__device__ __forceinline__ uint32_t smem_u32(const void* p) {
    uint32_t a;
    asm("{ .reg .u64 t; cvta.to.shared.u64 t, %1; cvt.u32.u64 %0, t; }" : "=r"(a) : "l"(p));
    return a;
}
__device__ __forceinline__ void cp16(uint32_t smem_dst, const void* gmem_src) {
    asm volatile("cp.async.cg.shared.global [%0], [%1], 16;" :: "r"(smem_dst), "l"(gmem_src));
}
#define CP_COMMIT() asm volatile("cp.async.commit_group;" ::: "memory")
#define CP_WAIT1()  asm volatile("cp.async.wait_group 1;" ::: "memory")

__device__ __forceinline__ void ldsm_x4(uint32_t (&r)[4], uint32_t addr) {
    asm volatile("ldmatrix.sync.aligned.m8n8.x4.shared.b16 {%0,%1,%2,%3}, [%4];"
                 : "=r"(r[0]), "=r"(r[1]), "=r"(r[2]), "=r"(r[3]) : "r"(addr));
}
__device__ __forceinline__ void mma_bf16(float (&d)[4], const uint32_t (&a)[4],
                                         uint32_t b0, uint32_t b1) {
    asm volatile(
        "mma.sync.aligned.m16n8k16.row.col.f32.bf16.bf16.f32 "
        "{%0,%1,%2,%3}, {%4,%5,%6,%7}, {%8,%9}, {%0,%1,%2,%3};"
        : "+f"(d[0]), "+f"(d[1]), "+f"(d[2]), "+f"(d[3])
        : "r"(a[0]), "r"(a[1]), "r"(a[2]), "r"(a[3]), "r"(b0), "r"(b1));
}
__device__ __forceinline__ void mma_s8(uint32_t (&d)[4], const uint32_t (&a)[4],
                                       uint32_t b0, uint32_t b1) {
    asm volatile(
        "mma.sync.aligned.m16n8k32.row.col.s32.s8.s8.s32 "
        "{%0,%1,%2,%3}, {%4,%5,%6,%7}, {%8,%9}, {%0,%1,%2,%3};"
        : "+r"(d[0]), "+r"(d[1]), "+r"(d[2]), "+r"(d[3])
        : "r"(a[0]), "r"(a[1]), "r"(a[2]), "r"(a[3]), "r"(b0), "r"(b1));
}

// SW128 swizzle (Swizzle<3,4,3>) — tile bases must be 1024B aligned
#define SWZ(o) ((o) ^ (((o) >> 3) & 0x70))

__device__ __forceinline__ int8_t q8(float v) {
    float r = rintf(v);
    r = fminf(127.f, fmaxf(-127.f, r));
    return (int8_t)r;
}

// ===================== merged conversion kernel =====================
static constexpr int XB = (BATCH * IN_F / 4) / 256;   // 32768 blocks
static constexpr int WB = (OUT_F * IN_F / 4) / 256;   //  4096 blocks

__global__ void convert_kernel(const float* __restrict__ x,
                               const int* __restrict__ wq,
                               const float* __restrict__ cent,
                               const float* __restrict__ alpha) {
    int bid = blockIdx.x;
    if (bid < XB) {
        size_t i = (size_t)bid * 256 + threadIdx.x;        // float4 index
        float a = alpha[0];
        bool fast = (a == 0.5f);
        float4 v = reinterpret_cast<const float4*>(x)[i];
        size_t e = i << 2;
        size_t row = e >> 11;                              // / IN_F
        size_t col = e & (IN_F - 1);
        float s[4] = {v.x, v.y, v.z, v.w};
        union { __nv_bfloat16 h[4]; uint2 u; } H;
        union { int8_t b[4]; uint32_t u; } LO8, HI8;
#pragma unroll
        for (int k = 0; k < 4; k++) {
            float t  = s[k];
            float at = fabsf(t);
            float p  = fast ? sqrtf(at) : powf(at, a);
            float sc = copysignf(p, t);
            H.h[k] = __float2bfloat16(sc);
            float lo = sc - __bfloat162float(H.h[k]);
            LO8.b[k] = q8(lo * 16384.0f);   // A_lo * 2^14
            HI8.b[k] = q8(sc * 32.0f);      // A_hi * 2^5
        }
        *reinterpret_cast<uint2*>(g_Abf + row * IN_F + col) = H.u;
        uint8_t* a8 = g_A8 + row * (2 * IN_F);
        *reinterpret_cast<uint32_t*>(a8 + col)        = LO8.u;
        *reinterpret_cast<uint32_t*>(a8 + IN_F + col) = HI8.u;
    } else {
        __shared__ float c[16];
        if (threadIdx.x < 16) c[threadIdx.x] = cent[threadIdx.x];
        __syncthreads();
        size_t i = (size_t)(bid - XB) * 256 + threadIdx.x; // int4 index
        int4 q = reinterpret_cast<const int4*>(wq)[i];
        size_t e = i << 2;
        size_t row = e >> 11;
        size_t col = e & (IN_F - 1);
        float w[4] = {c[q.x & 15], c[q.y & 15], c[q.z & 15], c[q.w & 15]};
        union { __nv_bfloat16 h[4]; uint2 u; } H;
        union { int8_t b[4]; uint32_t u; } HI8, LO8;
#pragma unroll
        for (int k = 0; k < 4; k++) {
            H.h[k] = __float2bfloat16(w[k]);
            float wf = __bfloat162float(H.h[k]);
            HI8.b[k] = q8(wf * 32.0f);                  // W_hi * 2^5
            LO8.b[k] = q8((w[k] - wf) * 16384.0f);      // W_lo * 2^14
        }
        *reinterpret_cast<uint2*>(g_Wbf + row * IN_F + col) = H.u;
        uint8_t* w8 = g_W8 + row * (2 * IN_F);
        *reinterpret_cast<uint32_t*>(w8 + col)        = HI8.u;
        *reinterpret_cast<uint32_t*>(w8 + IN_F + col) = LO8.u;
    }
}

// ===================== GEMM kernel =====================
// phase 1 (kc 0..31):  int8 K=4096, 128 elems (=128B) per kc
// phase 2 (kc 32..63): bf16 K=2048,  64 elems (=128B) per kc
static constexpr int BM = 128;
static constexpr int BN = 128;
static constexpr int STAGES = 3;
static constexpr int A_BYTES = BM * 128;          // 16 KiB (128B per row-chunk)
static constexpr int B_BYTES = BN * 128;          // 16 KiB
static constexpr int STG = A_BYTES + B_BYTES;     // 32 KiB
static constexpr int SMEM_TOTAL = STAGES * STG;   // 96 KiB
static constexpr int NKC8 = 32;                   // int8 chunks
static constexpr int NKC  = 64;                   // total chunks
static constexpr int NTHR = 256;                  // 8 warps: 4(m) x 2(n), 32x64 warp tile
static constexpr int NB_PER_M = OUT_F / BN;       // 16 n-blocks
static constexpr int ROW_BYTES = 2 * IN_F;        // 4096B row stride (all 4 arrays)

__global__ void __launch_bounds__(NTHR, 2)
gemm_kernel(float* __restrict__ out, const float* __restrict__ alpha) {
    extern __shared__ char smem_raw[];
    uint32_t sb = smem_u32(smem_raw);

    const int tid = threadIdx.x;
    const int wid = tid >> 5, lane = tid & 31;
    const int warp_m = wid & 3, warp_n = wid >> 2;          // 4 x 2 warps
    const int mb = blockIdx.x >> 4, nb = blockIdx.x & 15;   // n-minor: L2 A reuse
    const int m0 = mb * BM, n0 = nb * BN;

    const char* gA8 = (const char*)(g_A8 + (size_t)m0 * ROW_BYTES);
    const char* gAb = (const char*)(g_Abf + (size_t)m0 * IN_F);   // 4096B rows
    const char* gW8 = (const char*)(g_W8 + (size_t)n0 * ROW_BYTES);
    const char* gWb = (const char*)(g_Wbf + (size_t)n0 * IN_F);

    // ---- ldmatrix per-lane address components (byte-identical for both phases) ----
    const int a_row  = warp_m * 32 + (lane & 15);
    const int a_ext  = (lane >> 4) * 16;
    const int b_row  = warp_n * 64 + (lane & 7) + ((lane >> 4) << 3);
    const int b_ext  = ((lane >> 3) & 1) * 16;

    auto load_stage = [&](int slot, int kc) {
        const char* bA; const char* bB; int co;
        if (kc < NKC8) { bA = gA8; bB = gW8; co = kc * 128; }
        else           { bA = gAb; bB = gWb; co = (kc - NKC8) * 128; }
        uint32_t sA = sb + slot * STG;
        uint32_t sB = sA + A_BYTES;
#pragma unroll
        for (int i = 0; i < 4; i++) {
            int c = tid + i * NTHR;
            int row = c >> 3, col = c & 7;
            cp16(sA + SWZ(row * 128 + col * 16), bA + (size_t)row * ROW_BYTES + co + col * 16);
        }
#pragma unroll
        for (int i = 0; i < 4; i++) {
            int c = tid + i * NTHR;
            int row = c >> 3, col = c & 7;
            cp16(sB + SWZ(row * 128 + col * 16), bB + (size_t)row * ROW_BYTES + co + col * 16);
        }
    };

    // ---- prologue ----
    load_stage(0, 0); CP_COMMIT();
    load_stage(1, 1); CP_COMMIT();

    int slot = 0, nslot = 2;

    // ================= phase 1: int8 correction GEMM =================
    uint32_t accu[2][8][4];
#pragma unroll
    for (int im = 0; im < 2; im++)
#pragma unroll
        for (int in = 0; in < 8; in++)
#pragma unroll
            for (int r = 0; r < 4; r++) accu[im][in][r] = 0u;

    for (int kc = 0; kc < NKC8; kc++) {
        CP_WAIT1();
        __syncthreads();
        int nkc = kc + STAGES - 1;
        if (nkc < NKC) load_stage(nslot, nkc);
        CP_COMMIT();

        uint32_t sA = sb + slot * STG;
        uint32_t sB = sA + A_BYTES;
#pragma unroll
        for (int ks = 0; ks < 4; ks++) {   // ks = one k32 step (32 bytes)
            uint32_t af[2][4], bfr[4][4];
#pragma unroll
            for (int im = 0; im < 2; im++)
                ldsm_x4(af[im], sA + SWZ((a_row + im * 16) * 128 + ks * 32 + a_ext));
#pragma unroll
            for (int jn = 0; jn < 4; jn++)
                ldsm_x4(bfr[jn], sB + SWZ((b_row + jn * 16) * 128 + ks * 32 + b_ext));
#pragma unroll
            for (int im = 0; im < 2; im++)
#pragma unroll
                for (int jn = 0; jn < 4; jn++) {
                    mma_s8(accu[im][2 * jn + 0], af[im], bfr[jn][0], bfr[jn][1]);
                    mma_s8(accu[im][2 * jn + 1], af[im], bfr[jn][2], bfr[jn][3]);
                }
        }
        slot = (slot == STAGES - 1) ? 0 : slot + 1;
        nslot = (nslot == STAGES - 1) ? 0 : nslot + 1;
    }

    // ---- convert int32 correction -> fp32 acc (scale 2^-19) ----
    float acc[2][8][4];
    const float CS = 1.0f / 524288.0f;
#pragma unroll
    for (int im = 0; im < 2; im++)
#pragma unroll
        for (int in = 0; in < 8; in++)
#pragma unroll
            for (int r = 0; r < 4; r++)
                acc[im][in][r] = (float)(int)accu[im][in][r] * CS;

    // ================= phase 2: bf16 main GEMM =================
    for (int kc = NKC8; kc < NKC; kc++) {
        CP_WAIT1();
        __syncthreads();
        int nkc = kc + STAGES - 1;
        if (nkc < NKC) load_stage(nslot, nkc);
        CP_COMMIT();

        uint32_t sA = sb + slot * STG;
        uint32_t sB = sA + A_BYTES;
#pragma unroll
        for (int ks = 0; ks < 4; ks++) {   // ks = one k16 step (32 bytes)
            uint32_t af[2][4], bfr[4][4];
#pragma unroll
            for (int im = 0; im < 2; im++)
                ldsm_x4(af[im], sA + SWZ((a_row + im * 16) * 128 + ks * 32 + a_ext));
#pragma unroll
            for (int jn = 0; jn < 4; jn++)
                ldsm_x4(bfr[jn], sB + SWZ((b_row + jn * 16) * 128 + ks * 32 + b_ext));
#pragma unroll
            for (int im = 0; im < 2; im++)
#pragma unroll
                for (int jn = 0; jn < 4; jn++) {
                    mma_bf16(acc[im][2 * jn + 0], af[im], bfr[jn][0], bfr[jn][1]);
                    mma_bf16(acc[im][2 * jn + 1], af[im], bfr[jn][2], bfr[jn][3]);
                }
        }
        slot = (slot == STAGES - 1) ? 0 : slot + 1;
        nslot = (nslot == STAGES - 1) ? 0 : nslot + 1;
    }

    // ---- epilogue: y = sign(d) * |d|^(1/a) ----
    float a = alpha[0];
    bool fast = (a == 0.5f);
    float inv = 1.0f / a;
    const int er = m0 + warp_m * 32 + (lane >> 2);
    const int ec = n0 + warp_n * 64 + (lane & 3) * 2;
#pragma unroll
    for (int im = 0; im < 2; im++) {
#pragma unroll
        for (int in = 0; in < 8; in++) {
            float d0 = acc[im][in][0], d1 = acc[im][in][1];
            float d2 = acc[im][in][2], d3 = acc[im][in][3];
            float2 v01, v23;
            if (fast) {
                v01.x = d0 * fabsf(d0); v01.y = d1 * fabsf(d1);
                v23.x = d2 * fabsf(d2); v23.y = d3 * fabsf(d3);
            } else {
                v01.x = copysignf(powf(fabsf(d0), inv), d0);
                v01.y = copysignf(powf(fabsf(d1), inv), d1);
                v23.x = copysignf(powf(fabsf(d2), inv), d2);
                v23.y = copysignf(powf(fabsf(d3), inv), d3);
            }
            int jn = in >> 1, b = in & 1;
            int row = er + im * 16;
            int col = ec + jn * 16 + b * 8;
            *reinterpret_cast<float2*>(out + (size_t)row * OUT_F + col) = v01;
            *reinterpret_cast<float2*>(out + (size_t)(row + 8) * OUT_F + col) = v23;
        }
    }
}

// ===================== launch =====================
extern "C" void kernel_launch(void* const* d_in, const int* in_sizes, int n_in,
                              void* d_out, int out_size) {
    const float* x = nullptr;
    const float* cent = nullptr;
    const float* alpha = nullptr;
    const int*   wq = nullptr;
    for (int i = 0; i < n_in; i++) {
        long s = in_sizes[i];
        if      (s == (long)BATCH * IN_F) x     = (const float*)d_in[i];
        else if (s == 16)                 cent  = (const float*)d_in[i];
        else if (s == 1)                  alpha = (const float*)d_in[i];
        else if (s == (long)OUT_F * IN_F) wq    = (const int*)d_in[i];
    }

    cudaFuncSetAttribute(gemm_kernel, cudaFuncAttributeMaxDynamicSharedMemorySize, SMEM_TOTAL);

    convert_kernel<<<XB + WB, 256>>>(x, wq, cent, alpha);
    gemm_kernel<<<(BATCH / BM) * NB_PER_M, NTHR, SMEM_TOTAL>>>((float*)d_out, alpha);
}

// round 9
// speedup vs baseline: 3.4965x; 3.4965x over previous
#include <cuda_runtime.h>
#include <cuda_fp16.h>
#include <cstdint>
#include <cstddef>

// ===================== problem dims =====================
static constexpr int BATCH = 16384;
static constexpr int IN_F  = 2048;
static constexpr int OUT_F = 2048;

// C = (A_hi + A_lo) . W1   all fp16, fp32 accum
//   A_hi = fp16(x_scaled), A_lo = fp16(x_scaled - A_hi)  (residual ~u^2)
//   W1   = fp16(W)                                        (err ~2e-4 effective)

// ===================== device scratch =====================
__device__ __half g_A[(size_t)BATCH * 2 * IN_F];   // 128 MiB  [hi(2048) | lo(2048)] per row
__device__ __half g_W[(size_t)OUT_F * IN_F];       //   8 MiB

// ===================== helpers =====================
__device__ __forceinline__ uint32_t smem_u32(const void* p) {
    uint32_t a;
    asm("{ .reg .u64 t; cvta.to.shared.u64 t, %1; cvt.u32.u64 %0, t; }" : "=r"(a) : "l"(p));
    return a;
}
__device__ __forceinline__ void cp16(uint32_t smem_dst, const void* gmem_src) {
    asm volatile("cp.async.cg.shared.global [%0], [%1], 16;" :: "r"(smem_dst), "l"(gmem_src));
}
#define CP_COMMIT() asm volatile("cp.async.commit_group;" ::: "memory")
#define CP_WAIT1()  asm volatile("cp.async.wait_group 1;" ::: "memory")

__device__ __forceinline__ void ldsm_x4(uint32_t (&r)[4], uint32_t addr) {
    asm volatile("ldmatrix.sync.aligned.m8n8.x4.shared.b16 {%0,%1,%2,%3}, [%4];"
                 : "=r"(r[0]), "=r"(r[1]), "=r"(r[2]), "=r"(r[3]) : "r"(addr));
}
__device__ __forceinline__ void mma_f16(float (&d)[4], const uint32_t (&a)[4],
                                        uint32_t b0, uint32_t b1) {
    asm volatile(
        "mma.sync.aligned.m16n8k16.row.col.f32.f16.f16.f32 "
        "{%0,%1,%2,%3}, {%4,%5,%6,%7}, {%8,%9}, {%0,%1,%2,%3};"
        : "+f"(d[0]), "+f"(d[1]), "+f"(d[2]), "+f"(d[3])
        : "r"(a[0]), "r"(a[1]), "r"(a[2]), "r"(a[3]), "r"(b0), "r"(b1));
}

// SW128 swizzle (Swizzle<3,4,3>) — tile bases must be 1024B aligned
#define SWZ(o) ((o) ^ (((o) >> 3) & 0x70))

// ===================== merged conversion kernel =====================
static constexpr int XB = (BATCH * IN_F / 4) / 256;   // 32768 blocks
static constexpr int WB = (OUT_F * IN_F / 4) / 256;   //  4096 blocks

__global__ void convert_kernel(const float* __restrict__ x,
                               const int* __restrict__ wq,
                               const float* __restrict__ cent,
                               const float* __restrict__ alpha) {
    int bid = blockIdx.x;
    if (bid < XB) {
        size_t i = (size_t)bid * 256 + threadIdx.x;        // float4 index
        float a = alpha[0];
        bool fast = (a == 0.5f);
        float4 v = reinterpret_cast<const float4*>(x)[i];
        size_t e = i << 2;
        size_t row = e >> 11;                              // / IN_F
        size_t col = e & (IN_F - 1);
        float s[4] = {v.x, v.y, v.z, v.w};
        union { __half h[4]; uint2 u; } H, L;
#pragma unroll
        for (int k = 0; k < 4; k++) {
            float t  = s[k];
            float at = fabsf(t);
            float p  = fast ? sqrtf(at) : powf(at, a);
            float sc = copysignf(p, t);
            H.h[k] = __float2half(sc);
            L.h[k] = __float2half(sc - __half2float(H.h[k]));
        }
        __half* base = g_A + row * (2 * IN_F) + col;
        *reinterpret_cast<uint2*>(base)        = H.u;
        *reinterpret_cast<uint2*>(base + IN_F) = L.u;
    } else {
        __shared__ float c[16];
        if (threadIdx.x < 16) c[threadIdx.x] = cent[threadIdx.x];
        __syncthreads();
        size_t i = (size_t)(bid - XB) * 256 + threadIdx.x; // int4 index
        int4 q = reinterpret_cast<const int4*>(wq)[i];
        size_t e = i << 2;
        size_t row = e >> 11;
        size_t col = e & (IN_F - 1);
        union { __half h[4]; uint2 u; } H;
        H.h[0] = __float2half(c[q.x & 15]);
        H.h[1] = __float2half(c[q.y & 15]);
        H.h[2] = __float2half(c[q.z & 15]);
        H.h[3] = __float2half(c[q.w & 15]);
        *reinterpret_cast<uint2*>(g_W + row * IN_F + col) = H.u;
    }
}

// ===================== GEMM kernel (fp16 mma.sync, 3-stage cp.async, 2 CTA/SM) ============
static constexpr int BM = 128;
static constexpr int BN = 128;
static constexpr int STAGES = 3;
static constexpr int A_BYTES = BM * 128;          // 16 KiB (128B per row per kc)
static constexpr int B_BYTES = BN * 128;          // 16 KiB
static constexpr int STG = A_BYTES + B_BYTES;     // 32 KiB
static constexpr int SMEM_TOTAL = STAGES * STG;   // 96 KiB
static constexpr int NKC = 64;                    // K=4096 fp16: [hi | lo] terms
static constexpr int NTHR = 256;                  // 8 warps: 4(m) x 2(n), 32x64 warp tile
static constexpr int NB_PER_M = OUT_F / BN;       // 16 n-blocks
static constexpr int A_ROW_B = 2 * IN_F * 2;      // 8192 B
static constexpr int W_ROW_B = IN_F * 2;          // 4096 B

__global__ void __launch_bounds__(NTHR, 2)
gemm_kernel(float* __restrict__ out, const float* __restrict__ alpha) {
    extern __shared__ char smem_raw[];
    uint32_t sb = smem_u32(smem_raw);

    const int tid = threadIdx.x;
    const int wid = tid >> 5, lane = tid & 31;
    const int warp_m = wid & 3, warp_n = wid >> 2;          // 4 x 2 warps
    const int mb = blockIdx.x >> 4, nb = blockIdx.x & 15;   // n-minor: L2 A reuse
    const int m0 = mb * BM, n0 = nb * BN;

    const char* gA = (const char*)g_A + (size_t)m0 * A_ROW_B;
    const char* gW = (const char*)g_W + (size_t)n0 * W_ROW_B;

    // ---- ldmatrix per-lane address components ----
    const int a_row  = warp_m * 32 + (lane & 15);
    const int a_ext  = (lane >> 4) * 16;
    const int b_row  = warp_n * 64 + (lane & 7) + ((lane >> 4) << 3);
    const int b_ext  = ((lane >> 3) & 1) * 16;

    float acc[2][8][4];
#pragma unroll
    for (int im = 0; im < 2; im++)
#pragma unroll
        for (int in = 0; in < 8; in++)
#pragma unroll
            for (int r = 0; r < 4; r++) acc[im][in][r] = 0.0f;

    auto load_stage = [&](int slot, int kc) {
        int aoff = kc * 128;               // A: [hi|lo] K=4096, 128B per kc
        int boff = (kc & 31) * 128;        // W: same tile for kc and kc+32
        uint32_t sA = sb + slot * STG;
        uint32_t sB = sA + A_BYTES;
#pragma unroll
        for (int i = 0; i < 4; i++) {
            int c = tid + i * NTHR;
            int row = c >> 3, col = c & 7;
            cp16(sA + SWZ(row * 128 + col * 16), gA + (size_t)row * A_ROW_B + aoff + col * 16);
        }
#pragma unroll
        for (int i = 0; i < 4; i++) {
            int c = tid + i * NTHR;
            int row = c >> 3, col = c & 7;
            cp16(sB + SWZ(row * 128 + col * 16), gW + (size_t)row * W_ROW_B + boff + col * 16);
        }
    };

    // ---- prologue ----
    load_stage(0, 0); CP_COMMIT();
    load_stage(1, 1); CP_COMMIT();

    // ---- main loop ----
    int slot = 0, nslot = 2;
    for (int kc = 0; kc < NKC; kc++) {
        CP_WAIT1();
        __syncthreads();

        int nkc = kc + STAGES - 1;
        if (nkc < NKC) load_stage(nslot, nkc);
        CP_COMMIT();

        uint32_t sA = sb + slot * STG;
        uint32_t sB = sA + A_BYTES;

#pragma unroll
        for (int ks = 0; ks < 4; ks++) {
            uint32_t af[2][4], bfr[4][4];
#pragma unroll
            for (int im = 0; im < 2; im++)
                ldsm_x4(af[im], sA + SWZ((a_row + im * 16) * 128 + ks * 32 + a_ext));
#pragma unroll
            for (int jn = 0; jn < 4; jn++)
                ldsm_x4(bfr[jn], sB + SWZ((b_row + jn * 16) * 128 + ks * 32 + b_ext));
#pragma unroll
            for (int im = 0; im < 2; im++)
#pragma unroll
                for (int jn = 0; jn < 4; jn++) {
                    mma_f16(acc[im][2 * jn + 0], af[im], bfr[jn][0], bfr[jn][1]);
                    mma_f16(acc[im][2 * jn + 1], af[im], bfr[jn][2], bfr[jn][3]);
                }
        }

        slot = (slot == STAGES - 1) ? 0 : slot + 1;
        nslot = (nslot == STAGES - 1) ? 0 : nslot + 1;
    }

    // ---- epilogue: y = sign(d) * |d|^(1/a) ----
    float a = alpha[0];
    bool fast = (a == 0.5f);
    float inv = 1.0f / a;
    const int er = m0 + warp_m * 32 + (lane >> 2);
    const int ec = n0 + warp_n * 64 + (lane & 3) * 2;
#pragma unroll
    for (int im = 0; im < 2; im++) {
#pragma unroll
        for (int in = 0; in < 8; in++) {
            float d0 = acc[im][in][0], d1 = acc[im][in][1];
            float d2 = acc[im][in][2], d3 = acc[im][in][3];
            float2 v01, v23;
            if (fast) {
                v01.x = d0 * fabsf(d0); v01.y = d1 * fabsf(d1);
                v23.x = d2 * fabsf(d2); v23.y = d3 * fabsf(d3);
            } else {
                v01.x = copysignf(powf(fabsf(d0), inv), d0);
                v01.y = copysignf(powf(fabsf(d1), inv), d1);
                v23.x = copysignf(powf(fabsf(d2), inv), d2);
                v23.y = copysignf(powf(fabsf(d3), inv), d3);
            }
            int jn = in >> 1, b = in & 1;
            int row = er + im * 16;
            int col = ec + jn * 16 + b * 8;
            *reinterpret_cast<float2*>(out + (size_t)row * OUT_F + col) = v01;
            *reinterpret_cast<float2*>(out + (size_t)(row + 8) * OUT_F + col) = v23;
        }
    }
}

// ===================== launch =====================
extern "C" void kernel_launch(void* const* d_in, const int* in_sizes, int n_in,
                              void* d_out, int out_size) {
    const float* x = nullptr;
    const float* cent = nullptr;
    const float* alpha = nullptr;
    const int*   wq = nullptr;
    for (int i = 0; i < n_in; i++) {
        long s = in_sizes[i];
        if      (s == (long)BATCH * IN_F) x     = (const float*)d_in[i];
        else if (s == 16)                 cent  = (const float*)d_in[i];
        else if (s == 1)                  alpha = (const float*)d_in[i];
        else if (s == (long)OUT_F * IN_F) wq    = (const int*)d_in[i];
    }

    cudaFuncSetAttribute(gemm_kernel, cudaFuncAttributeMaxDynamicSharedMemorySize, SMEM_TOTAL);

    convert_kernel<<<XB + WB, 256>>>(x, wq, cent, alpha);
    gemm_kernel<<<(BATCH / BM) * NB_PER_M, NTHR, SMEM_TOTAL>>>((float*)d_out, alpha);
}

// round 10
// speedup vs baseline: 6.0197x; 1.7216x over previous
#include <cuda_runtime.h>
#include <cuda_fp16.h>
#include <cstdint>
#include <cstddef>

// ===================== problem dims =====================
static constexpr int BATCH = 16384;
static constexpr int IN_F  = 2048;
static constexpr int OUT_F = 2048;

// C = A . W   single-term fp16 x fp16, fp32 accum.
// Error budget: A-rounding + W-rounding in quadrature -> d ~2.3e-4, y ~4.7e-4 < 1e-3.

// ===================== device scratch =====================
__device__ __half g_A[(size_t)BATCH * IN_F];   // 64 MiB
__device__ __half g_W[(size_t)OUT_F * IN_F];   //  8 MiB

// ===================== helpers =====================
__device__ __forceinline__ uint32_t smem_u32(const void* p) {
    uint32_t a;
    asm("{ .reg .u64 t; cvta.to.shared.u64 t, %1; cvt.u32.u64 %0, t; }" : "=r"(a) : "l"(p));
    return a;
}
__device__ __forceinline__ void cp16(uint32_t smem_dst, const void* gmem_src) {
    asm volatile("cp.async.cg.shared.global [%0], [%1], 16;" :: "r"(smem_dst), "l"(gmem_src));
}
#define CP_COMMIT() asm volatile("cp.async.commit_group;" ::: "memory")
#define CP_WAIT1()  asm volatile("cp.async.wait_group 1;" ::: "memory")

__device__ __forceinline__ void ldsm_x4(uint32_t (&r)[4], uint32_t addr) {
    asm volatile("ldmatrix.sync.aligned.m8n8.x4.shared.b16 {%0,%1,%2,%3}, [%4];"
                 : "=r"(r[0]), "=r"(r[1]), "=r"(r[2]), "=r"(r[3]) : "r"(addr));
}
__device__ __forceinline__ void mma_f16(float (&d)[4], const uint32_t (&a)[4],
                                        uint32_t b0, uint32_t b1) {
    asm volatile(
        "mma.sync.aligned.m16n8k16.row.col.f32.f16.f16.f32 "
        "{%0,%1,%2,%3}, {%4,%5,%6,%7}, {%8,%9}, {%0,%1,%2,%3};"
        : "+f"(d[0]), "+f"(d[1]), "+f"(d[2]), "+f"(d[3])
        : "r"(a[0]), "r"(a[1]), "r"(a[2]), "r"(a[3]), "r"(b0), "r"(b1));
}

// SW128 swizzle (Swizzle<3,4,3>) — tile bases must be 1024B aligned
#define SWZ(o) ((o) ^ (((o) >> 3) & 0x70))

// ===================== merged conversion kernel =====================
static constexpr int XB = (BATCH * IN_F / 4) / 256;   // 32768 blocks
static constexpr int WB = (OUT_F * IN_F / 4) / 256;   //  4096 blocks

__global__ void convert_kernel(const float* __restrict__ x,
                               const int* __restrict__ wq,
                               const float* __restrict__ cent,
                               const float* __restrict__ alpha) {
    int bid = blockIdx.x;
    if (bid < XB) {
        size_t i = (size_t)bid * 256 + threadIdx.x;        // float4 index
        float a = alpha[0];
        bool fast = (a == 0.5f);
        float4 v = reinterpret_cast<const float4*>(x)[i];
        float s[4] = {v.x, v.y, v.z, v.w};
        union { __half h[4]; uint2 u; } H;
#pragma unroll
        for (int k = 0; k < 4; k++) {
            float t  = s[k];
            float at = fabsf(t);
            float p  = fast ? sqrtf(at) : powf(at, a);
            H.h[k] = __float2half(copysignf(p, t));
        }
        reinterpret_cast<uint2*>(g_A)[i] = H.u;
    } else {
        __shared__ float c[16];
        if (threadIdx.x < 16) c[threadIdx.x] = cent[threadIdx.x];
        __syncthreads();
        size_t i = (size_t)(bid - XB) * 256 + threadIdx.x; // int4 index
        int4 q = reinterpret_cast<const int4*>(wq)[i];
        union { __half h[4]; uint2 u; } H;
        H.h[0] = __float2half(c[q.x & 15]);
        H.h[1] = __float2half(c[q.y & 15]);
        H.h[2] = __float2half(c[q.z & 15]);
        H.h[3] = __float2half(c[q.w & 15]);
        reinterpret_cast<uint2*>(g_W)[i] = H.u;
    }
}

// ===================== GEMM kernel (fp16 mma.sync, 3-stage cp.async, 2 CTA/SM) ============
static constexpr int BM = 128;
static constexpr int BN = 128;
static constexpr int STAGES = 3;
static constexpr int A_BYTES = BM * 128;          // 16 KiB (128B per row per kc)
static constexpr int B_BYTES = BN * 128;          // 16 KiB
static constexpr int STG = A_BYTES + B_BYTES;     // 32 KiB
static constexpr int SMEM_TOTAL = STAGES * STG;   // 96 KiB
static constexpr int NKC = 32;                    // K=2048 fp16, 64 elems (128B) per kc
static constexpr int NTHR = 256;                  // 8 warps: 4(m) x 2(n), 32x64 warp tile
static constexpr int NB_PER_M = OUT_F / BN;       // 16 n-blocks
static constexpr int ROW_B = IN_F * 2;            // 4096 B (both A and W)

__global__ void __launch_bounds__(NTHR, 2)
gemm_kernel(float* __restrict__ out, const float* __restrict__ alpha) {
    extern __shared__ char smem_raw[];
    uint32_t sb = smem_u32(smem_raw);

    const int tid = threadIdx.x;
    const int wid = tid >> 5, lane = tid & 31;
    const int warp_m = wid & 3, warp_n = wid >> 2;          // 4 x 2 warps
    const int mb = blockIdx.x >> 4, nb = blockIdx.x & 15;   // n-minor: L2 A reuse
    const int m0 = mb * BM, n0 = nb * BN;

    const char* gA = (const char*)g_A + (size_t)m0 * ROW_B;
    const char* gW = (const char*)g_W + (size_t)n0 * ROW_B;

    // ---- ldmatrix per-lane address components ----
    const int a_row  = warp_m * 32 + (lane & 15);
    const int a_ext  = (lane >> 4) * 16;
    const int b_row  = warp_n * 64 + (lane & 7) + ((lane >> 4) << 3);
    const int b_ext  = ((lane >> 3) & 1) * 16;

    float acc[2][8][4];
#pragma unroll
    for (int im = 0; im < 2; im++)
#pragma unroll
        for (int in = 0; in < 8; in++)
#pragma unroll
            for (int r = 0; r < 4; r++) acc[im][in][r] = 0.0f;

    auto load_stage = [&](int slot, int kc) {
        int off = kc * 128;
        uint32_t sA = sb + slot * STG;
        uint32_t sB = sA + A_BYTES;
#pragma unroll
        for (int i = 0; i < 4; i++) {
            int c = tid + i * NTHR;
            int row = c >> 3, col = c & 7;
            cp16(sA + SWZ(row * 128 + col * 16), gA + (size_t)row * ROW_B + off + col * 16);
        }
#pragma unroll
        for (int i = 0; i < 4; i++) {
            int c = tid + i * NTHR;
            int row = c >> 3, col = c & 7;
            cp16(sB + SWZ(row * 128 + col * 16), gW + (size_t)row * ROW_B + off + col * 16);
        }
    };

    // ---- prologue ----
    load_stage(0, 0); CP_COMMIT();
    load_stage(1, 1); CP_COMMIT();

    // ---- main loop ----
    int slot = 0, nslot = 2;
    for (int kc = 0; kc < NKC; kc++) {
        CP_WAIT1();
        __syncthreads();

        int nkc = kc + STAGES - 1;
        if (nkc < NKC) load_stage(nslot, nkc);
        CP_COMMIT();

        uint32_t sA = sb + slot * STG;
        uint32_t sB = sA + A_BYTES;

#pragma unroll
        for (int ks = 0; ks < 4; ks++) {
            uint32_t af[2][4], bfr[4][4];
#pragma unroll
            for (int im = 0; im < 2; im++)
                ldsm_x4(af[im], sA + SWZ((a_row + im * 16) * 128 + ks * 32 + a_ext));
#pragma unroll
            for (int jn = 0; jn < 4; jn++)
                ldsm_x4(bfr[jn], sB + SWZ((b_row + jn * 16) * 128 + ks * 32 + b_ext));
#pragma unroll
            for (int im = 0; im < 2; im++)
#pragma unroll
                for (int jn = 0; jn < 4; jn++) {
                    mma_f16(acc[im][2 * jn + 0], af[im], bfr[jn][0], bfr[jn][1]);
                    mma_f16(acc[im][2 * jn + 1], af[im], bfr[jn][2], bfr[jn][3]);
                }
        }

        slot = (slot == STAGES - 1) ? 0 : slot + 1;
        nslot = (nslot == STAGES - 1) ? 0 : nslot + 1;
    }

    // ---- epilogue: y = sign(d) * |d|^(1/a) ----
    float a = alpha[0];
    bool fast = (a == 0.5f);
    float inv = 1.0f / a;
    const int er = m0 + warp_m * 32 + (lane >> 2);
    const int ec = n0 + warp_n * 64 + (lane & 3) * 2;
#pragma unroll
    for (int im = 0; im < 2; im++) {
#pragma unroll
        for (int in = 0; in < 8; in++) {
            float d0 = acc[im][in][0], d1 = acc[im][in][1];
            float d2 = acc[im][in][2], d3 = acc[im][in][3];
            float2 v01, v23;
            if (fast) {
                v01.x = d0 * fabsf(d0); v01.y = d1 * fabsf(d1);
                v23.x = d2 * fabsf(d2); v23.y = d3 * fabsf(d3);
            } else {
                v01.x = copysignf(powf(fabsf(d0), inv), d0);
                v01.y = copysignf(powf(fabsf(d1), inv), d1);
                v23.x = copysignf(powf(fabsf(d2), inv), d2);
                v23.y = copysignf(powf(fabsf(d3), inv), d3);
            }
            int jn = in >> 1, b = in & 1;
            int row = er + im * 16;
            int col = ec + jn * 16 + b * 8;
            *reinterpret_cast<float2*>(out + (size_t)row * OUT_F + col) = v01;
            *reinterpret_cast<float2*>(out + (size_t)(row + 8) * OUT_F + col) = v23;
        }
    }
}

// ===================== launch =====================
extern "C" void kernel_launch(void* const* d_in, const int* in_sizes, int n_in,
                              void* d_out, int out_size) {
    const float* x = nullptr;
    const float* cent = nullptr;
    const float* alpha = nullptr;
    const int*   wq = nullptr;
    for (int i = 0; i < n_in; i++) {
        long s = in_sizes[i];
        if      (s == (long)BATCH * IN_F) x     = (const float*)d_in[i];
        else if (s == 16)                 cent  = (const float*)d_in[i];
        else if (s == 1)                  alpha = (const float*)d_in[i];
        else if (s == (long)OUT_F * IN_F) wq    = (const int*)d_in[i];
    }

    cudaFuncSetAttribute(gemm_kernel, cudaFuncAttributeMaxDynamicSharedMemorySize, SMEM_TOTAL);

    convert_kernel<<<XB + WB, 256>>>(x, wq, cent, alpha);
    gemm_kernel<<<(BATCH / BM) * NB_PER_M, NTHR, SMEM_TOTAL>>>((float*)d_out, alpha);
}

// round 11
// speedup vs baseline: 6.2000x; 1.0299x over previous
#include <cuda_runtime.h>
#include <cuda_fp16.h>
#include <cstdint>
#include <cstddef>

// ===================== problem dims =====================
static constexpr int BATCH = 16384;
static constexpr int IN_F  = 2048;
static constexpr int OUT_F = 2048;

// C = A . W   single fp16 x fp16 GEMM, fp32 accum.  y = signed_pow(d, 1/a) epilogue.

// ===================== device scratch =====================
__device__ __half g_A[(size_t)BATCH * IN_F];   // 64 MiB
__device__ __half g_W[(size_t)OUT_F * IN_F];   //  8 MiB

// ===================== helpers =====================
__device__ __forceinline__ uint32_t smem_u32(const void* p) {
    uint32_t a;
    asm("{ .reg .u64 t; cvta.to.shared.u64 t, %1; cvt.u32.u64 %0, t; }" : "=r"(a) : "l"(p));
    return a;
}
__device__ __forceinline__ void cp16(uint32_t smem_dst, const void* gmem_src) {
    asm volatile("cp.async.cg.shared.global [%0], [%1], 16;" :: "r"(smem_dst), "l"(gmem_src));
}
#define CP_COMMIT() asm volatile("cp.async.commit_group;" ::: "memory")
#define CP_WAIT1()  asm volatile("cp.async.wait_group 1;" ::: "memory")

__device__ __forceinline__ void ldsm_x4(uint32_t (&r)[4], uint32_t addr) {
    asm volatile("ldmatrix.sync.aligned.m8n8.x4.shared.b16 {%0,%1,%2,%3}, [%4];"
                 : "=r"(r[0]), "=r"(r[1]), "=r"(r[2]), "=r"(r[3]) : "r"(addr));
}
__device__ __forceinline__ void mma_f16(float (&d)[4], const uint32_t (&a)[4],
                                        uint32_t b0, uint32_t b1) {
    asm volatile(
        "mma.sync.aligned.m16n8k16.row.col.f32.f16.f16.f32 "
        "{%0,%1,%2,%3}, {%4,%5,%6,%7}, {%8,%9}, {%0,%1,%2,%3};"
        : "+f"(d[0]), "+f"(d[1]), "+f"(d[2]), "+f"(d[3])
        : "r"(a[0]), "r"(a[1]), "r"(a[2]), "r"(a[3]), "r"(b0), "r"(b1));
}
__device__ __forceinline__ float fast_sqrt(float x) {
    float r;
    asm("sqrt.approx.f32 %0, %1;" : "=f"(r) : "f"(x));
    return r;
}

// SW128 swizzle (Swizzle<3,4,3>) — tile bases must be 1024B aligned
#define SWZ(o) ((o) ^ (((o) >> 3) & 0x70))

// ===================== merged conversion kernel =====================
static constexpr int XB = (BATCH * IN_F / 4) / 256;   // 32768 blocks
static constexpr int WB = (OUT_F * IN_F / 4) / 256;   //  4096 blocks

__global__ void convert_kernel(const float* __restrict__ x,
                               const int* __restrict__ wq,
                               const float* __restrict__ cent,
                               const float* __restrict__ alpha) {
    int bid = blockIdx.x;
    if (bid < XB) {
        size_t i = (size_t)bid * 256 + threadIdx.x;        // float4 index
        float a = alpha[0];
        bool fast = (a == 0.5f);
        float4 v = reinterpret_cast<const float4*>(x)[i];
        float s[4] = {v.x, v.y, v.z, v.w};
        union { __half h[4]; uint2 u; } H;
#pragma unroll
        for (int k = 0; k < 4; k++) {
            float t  = s[k];
            float at = fabsf(t);
            float p  = fast ? fast_sqrt(at) : powf(at, a);
            H.h[k] = __float2half(copysignf(p, t));
        }
        reinterpret_cast<uint2*>(g_A)[i] = H.u;
    } else {
        __shared__ float c[16];
        if (threadIdx.x < 16) c[threadIdx.x] = cent[threadIdx.x];
        __syncthreads();
        size_t i = (size_t)(bid - XB) * 256 + threadIdx.x; // int4 index
        int4 q = reinterpret_cast<const int4*>(wq)[i];
        union { __half h[4]; uint2 u; } H;
        H.h[0] = __float2half(c[q.x & 15]);
        H.h[1] = __float2half(c[q.y & 15]);
        H.h[2] = __float2half(c[q.z & 15]);
        H.h[3] = __float2half(c[q.w & 15]);
        reinterpret_cast<uint2*>(g_W)[i] = H.u;
    }
}

// ===================== GEMM kernel (fp16 mma.sync, 3-stage cp.async, 2 CTA/SM) ============
static constexpr int BM = 128;
static constexpr int BN = 128;
static constexpr int STAGES = 3;
static constexpr int A_BYTES = BM * 128;          // 16 KiB (128B per row per kc)
static constexpr int B_BYTES = BN * 128;          // 16 KiB
static constexpr int STG = A_BYTES + B_BYTES;     // 32 KiB
static constexpr int SMEM_TOTAL = STAGES * STG;   // 96 KiB
static constexpr int NKC = 32;                    // K=2048 fp16, 64 elems (128B) per kc
static constexpr int NTHR = 256;                  // 8 warps: 4(m) x 2(n), 32x64 warp tile
static constexpr int NB_PER_M = OUT_F / BN;       // 16 n-blocks
static constexpr int ROW_B = IN_F * 2;            // 4096 B (both A and W)

__global__ void __launch_bounds__(NTHR, 2)
gemm_kernel(float* __restrict__ out, const float* __restrict__ alpha) {
    extern __shared__ char smem_raw[];
    uint32_t sb = smem_u32(smem_raw);

    const int tid = threadIdx.x;
    const int wid = tid >> 5, lane = tid & 31;
    const int warp_m = wid & 3, warp_n = wid >> 2;          // 4 x 2 warps
    const int mb = blockIdx.x >> 4, nb = blockIdx.x & 15;   // n-minor: L2 A reuse
    const int m0 = mb * BM, n0 = nb * BN;

    const char* gA = (const char*)g_A + (size_t)m0 * ROW_B;
    const char* gW = (const char*)g_W + (size_t)n0 * ROW_B;

    // ---- hoisted cp.async addressing (4 chunks/thread for A and B, same dst pattern) ----
    uint32_t dst[4];
    const char* srcA[4];
    const char* srcB[4];
#pragma unroll
    for (int i = 0; i < 4; i++) {
        int c = tid + i * NTHR;
        int row = c >> 3, col = c & 7;
        dst[i]  = SWZ(row * 128 + col * 16);
        srcA[i] = gA + (size_t)row * ROW_B + col * 16;
        srcB[i] = gW + (size_t)row * ROW_B + col * 16;
    }

    // ---- ldmatrix per-lane address components ----
    const int a_row  = warp_m * 32 + (lane & 15);
    const int a_ext  = (lane >> 4) * 16;
    const int b_row  = warp_n * 64 + (lane & 7) + ((lane >> 4) << 3);
    const int b_ext  = ((lane >> 3) & 1) * 16;

    float acc[2][8][4];
#pragma unroll
    for (int im = 0; im < 2; im++)
#pragma unroll
        for (int in = 0; in < 8; in++)
#pragma unroll
            for (int r = 0; r < 4; r++) acc[im][in][r] = 0.0f;

    auto load_stage = [&](int slot, int kc) {
        int off = kc * 128;
        uint32_t sA = sb + slot * STG;
        uint32_t sB = sA + A_BYTES;
#pragma unroll
        for (int i = 0; i < 4; i++) cp16(sA + dst[i], srcA[i] + off);
#pragma unroll
        for (int i = 0; i < 4; i++) cp16(sB + dst[i], srcB[i] + off);
    };

    // ---- prologue ----
    load_stage(0, 0); CP_COMMIT();
    load_stage(1, 1); CP_COMMIT();

    // ---- main loop ----
    int slot = 0, nslot = 2;
    for (int kc = 0; kc < NKC; kc++) {
        CP_WAIT1();
        __syncthreads();

        uint32_t sA = sb + slot * STG;
        uint32_t sB = sA + A_BYTES;

        // ---- ks = 0 first: start tensor work immediately after barrier ----
        {
            uint32_t af[2][4], bfr[4][4];
#pragma unroll
            for (int im = 0; im < 2; im++)
                ldsm_x4(af[im], sA + SWZ((a_row + im * 16) * 128 + a_ext));
#pragma unroll
            for (int jn = 0; jn < 4; jn++)
                ldsm_x4(bfr[jn], sB + SWZ((b_row + jn * 16) * 128 + b_ext));
#pragma unroll
            for (int im = 0; im < 2; im++)
#pragma unroll
                for (int jn = 0; jn < 4; jn++) {
                    mma_f16(acc[im][2 * jn + 0], af[im], bfr[jn][0], bfr[jn][1]);
                    mma_f16(acc[im][2 * jn + 1], af[im], bfr[jn][2], bfr[jn][3]);
                }
        }

        // ---- prefetch stage kc+2 while ks=0 MMAs drain ----
        int nkc = kc + STAGES - 1;
        if (nkc < NKC) load_stage(nslot, nkc);
        CP_COMMIT();           // exactly one group per iteration (may be empty)

        // ---- ks = 1..3 ----
#pragma unroll
        for (int ks = 1; ks < 4; ks++) {
            uint32_t af[2][4], bfr[4][4];
#pragma unroll
            for (int im = 0; im < 2; im++)
                ldsm_x4(af[im], sA + SWZ((a_row + im * 16) * 128 + ks * 32 + a_ext));
#pragma unroll
            for (int jn = 0; jn < 4; jn++)
                ldsm_x4(bfr[jn], sB + SWZ((b_row + jn * 16) * 128 + ks * 32 + b_ext));
#pragma unroll
            for (int im = 0; im < 2; im++)
#pragma unroll
                for (int jn = 0; jn < 4; jn++) {
                    mma_f16(acc[im][2 * jn + 0], af[im], bfr[jn][0], bfr[jn][1]);
                    mma_f16(acc[im][2 * jn + 1], af[im], bfr[jn][2], bfr[jn][3]);
                }
        }

        slot = (slot == STAGES - 1) ? 0 : slot + 1;
        nslot = (nslot == STAGES - 1) ? 0 : nslot + 1;
    }

    // ---- epilogue: y = sign(d) * |d|^(1/a) ----
    float a = alpha[0];
    bool fast = (a == 0.5f);
    float inv = 1.0f / a;
    const int er = m0 + warp_m * 32 + (lane >> 2);
    const int ec = n0 + warp_n * 64 + (lane & 3) * 2;
#pragma unroll
    for (int im = 0; im < 2; im++) {
#pragma unroll
        for (int in = 0; in < 8; in++) {
            float d0 = acc[im][in][0], d1 = acc[im][in][1];
            float d2 = acc[im][in][2], d3 = acc[im][in][3];
            float2 v01, v23;
            if (fast) {
                v01.x = d0 * fabsf(d0); v01.y = d1 * fabsf(d1);
                v23.x = d2 * fabsf(d2); v23.y = d3 * fabsf(d3);
            } else {
                v01.x = copysignf(powf(fabsf(d0), inv), d0);
                v01.y = copysignf(powf(fabsf(d1), inv), d1);
                v23.x = copysignf(powf(fabsf(d2), inv), d2);
                v23.y = copysignf(powf(fabsf(d3), inv), d3);
            }
            int jn = in >> 1, b = in & 1;
            int row = er + im * 16;
            int col = ec + jn * 16 + b * 8;
            *reinterpret_cast<float2*>(out + (size_t)row * OUT_F + col) = v01;
            *reinterpret_cast<float2*>(out + (size_t)(row + 8) * OUT_F + col) = v23;
        }
    }
}

// ===================== launch =====================
extern "C" void kernel_launch(void* const* d_in, const int* in_sizes, int n_in,
                              void* d_out, int out_size) {
    const float* x = nullptr;
    const float* cent = nullptr;
    const float* alpha = nullptr;
    const int*   wq = nullptr;
    for (int i = 0; i < n_in; i++) {
        long s = in_sizes[i];
        if      (s == (long)BATCH * IN_F) x     = (const float*)d_in[i];
        else if (s == 16)                 cent  = (const float*)d_in[i];
        else if (s == 1)                  alpha = (const float*)d_in[i];
        else if (s == (long)OUT_F * IN_F) wq    = (const int*)d_in[i];
    }

    cudaFuncSetAttribute(gemm_kernel, cudaFuncAttributeMaxDynamicSharedMemorySize, SMEM_TOTAL);

    convert_kernel<<<XB + WB, 256>>>(x, wq, cent, alpha);
    gemm_kernel<<<(BATCH / BM) * NB_PER_M, NTHR, SMEM_TOTAL>>>((float*)d_out, alpha);
}

// round 13
// speedup vs baseline: 6.3067x; 1.0172x over previous
#include <cuda_runtime.h>
#include <cuda_fp16.h>
#include <cstdint>
#include <cstddef>

// ===================== problem dims =====================
static constexpr int BATCH = 16384;
static constexpr int IN_F  = 2048;
static constexpr int OUT_F = 2048;

// C = A . W   single fp16 x fp16 GEMM, fp32 accum.  y = signed_pow(d, 1/a) epilogue.

// ===================== device scratch =====================
__device__ __half g_A[(size_t)BATCH * IN_F];   // 64 MiB
__device__ __half g_W[(size_t)OUT_F * IN_F];   //  8 MiB

// ===================== helpers =====================
__device__ __forceinline__ uint32_t smem_u32(const void* p) {
    uint32_t a;
    asm("{ .reg .u64 t; cvta.to.shared.u64 t, %1; cvt.u32.u64 %0, t; }" : "=r"(a) : "l"(p));
    return a;
}
__device__ __forceinline__ void cp16(uint32_t smem_dst, const void* gmem_src) {
    asm volatile("cp.async.cg.shared.global [%0], [%1], 16;" :: "r"(smem_dst), "l"(gmem_src));
}
#define CP_COMMIT() asm volatile("cp.async.commit_group;" ::: "memory")
#define CP_WAIT1()  asm volatile("cp.async.wait_group 1;" ::: "memory")

__device__ __forceinline__ void ldsm_x4(uint32_t (&r)[4], uint32_t addr) {
    asm volatile("ldmatrix.sync.aligned.m8n8.x4.shared.b16 {%0,%1,%2,%3}, [%4];"
                 : "=r"(r[0]), "=r"(r[1]), "=r"(r[2]), "=r"(r[3]) : "r"(addr));
}
__device__ __forceinline__ void mma_f16(float (&d)[4], const uint32_t (&a)[4],
                                        uint32_t b0, uint32_t b1) {
    asm volatile(
        "mma.sync.aligned.m16n8k16.row.col.f32.f16.f16.f32 "
        "{%0,%1,%2,%3}, {%4,%5,%6,%7}, {%8,%9}, {%0,%1,%2,%3};"
        : "+f"(d[0]), "+f"(d[1]), "+f"(d[2]), "+f"(d[3])
        : "r"(a[0]), "r"(a[1]), "r"(a[2]), "r"(a[3]), "r"(b0), "r"(b1));
}
__device__ __forceinline__ float fast_sqrt(float x) {
    float r;
    asm("sqrt.approx.f32 %0, %1;" : "=f"(r) : "f"(x));
    return r;
}

// SW128 swizzle (Swizzle<3,4,3>) — tile bases must be 1024B aligned
#define SWZ(o) ((o) ^ (((o) >> 3) & 0x70))

// ===================== merged conversion kernel =====================
static constexpr int XB = (BATCH * IN_F / 4) / 256;   // 32768 blocks
static constexpr int WB = (OUT_F * IN_F / 4) / 256;   //  4096 blocks

__global__ void convert_kernel(const float* __restrict__ x,
                               const int* __restrict__ wq,
                               const float* __restrict__ cent,
                               const float* __restrict__ alpha) {
    int bid = blockIdx.x;
    if (bid < XB) {
        size_t i = (size_t)bid * 256 + threadIdx.x;        // float4 index
        float a = alpha[0];
        bool fast = (a == 0.5f);
        float4 v = reinterpret_cast<const float4*>(x)[i];
        float s[4] = {v.x, v.y, v.z, v.w};
        union { __half h[4]; uint2 u; } H;
#pragma unroll
        for (int k = 0; k < 4; k++) {
            float t  = s[k];
            float at = fabsf(t);
            float p  = fast ? fast_sqrt(at) : powf(at, a);
            H.h[k] = __float2half(copysignf(p, t));
        }
        reinterpret_cast<uint2*>(g_A)[i] = H.u;
    } else {
        __shared__ float c[16];
        if (threadIdx.x < 16) c[threadIdx.x] = cent[threadIdx.x];
        __syncthreads();
        size_t i = (size_t)(bid - XB) * 256 + threadIdx.x; // int4 index
        int4 q = reinterpret_cast<const int4*>(wq)[i];
        union { __half h[4]; uint2 u; } H;
        H.h[0] = __float2half(c[q.x & 15]);
        H.h[1] = __float2half(c[q.y & 15]);
        H.h[2] = __float2half(c[q.z & 15]);
        H.h[3] = __float2half(c[q.w & 15]);
        reinterpret_cast<uint2*>(g_W)[i] = H.u;
    }
}

// ===================== GEMM kernel (fp16 mma.sync, 3-stage cp.async, 2 CTA/SM) ============
static constexpr int BM = 128;
static constexpr int BN = 128;
static constexpr int STAGES = 3;
static constexpr int A_BYTES = BM * 128;          // 16 KiB (128B per row per kc)
static constexpr int B_BYTES = BN * 128;          // 16 KiB
static constexpr int STG = A_BYTES + B_BYTES;     // 32 KiB
static constexpr int SMEM_TOTAL = STAGES * STG;   // 96 KiB
static constexpr int NKC = 32;                    // K=2048 fp16, 64 elems (128B) per kc
static constexpr int NTHR = 256;                  // 8 warps: 4(m) x 2(n), 32x64 warp tile
static constexpr int NB_PER_M = OUT_F / BN;       // 16 n-blocks
static constexpr int ROW_B = IN_F * 2;            // 4096 B (both A and W)

__global__ void __launch_bounds__(NTHR, 2)
gemm_kernel(float* __restrict__ out, const float* __restrict__ alpha) {
    extern __shared__ char smem_raw[];
    uint32_t sb = smem_u32(smem_raw);

    const int tid = threadIdx.x;
    const int wid = tid >> 5, lane = tid & 31;
    const int warp_m = wid & 3, warp_n = wid >> 2;          // 4 x 2 warps
    const int mb = blockIdx.x >> 4, nb = blockIdx.x & 15;   // n-minor: L2 A reuse
    const int m0 = mb * BM, n0 = nb * BN;

    // cp.async base pointers (per-thread row/col folded in, offsets recomputed per use)
    const int ld_row = tid >> 3, ld_col = tid & 7;
    const char* baseA = (const char*)g_A + (size_t)(m0 + ld_row) * ROW_B + ld_col * 16;
    const char* baseW = (const char*)g_W + (size_t)(n0 + ld_row) * ROW_B + ld_col * 16;
    const uint32_t dst0 = SWZ(ld_row * 128 + ld_col * 16);  // +32*128 per i (rows +32)

    // ---- ldmatrix per-lane smem offsets (within a stage) ----
    const int a_row  = warp_m * 32 + (lane & 15);
    const int a_ext  = (lane >> 4) * 16;
    const int b_row  = warp_n * 64 + (lane & 7) + ((lane >> 4) << 3);
    const int b_ext  = ((lane >> 3) & 1) * 16;

    float acc[2][8][4];
#pragma unroll
    for (int im = 0; im < 2; im++)
#pragma unroll
        for (int in = 0; in < 8; in++)
#pragma unroll
            for (int r = 0; r < 4; r++) acc[im][in][r] = 0.0f;

    auto load_stage = [&](int slot, int kc) {
        int off = kc * 128;
        uint32_t sA = sb + slot * STG;
        uint32_t sB = sA + A_BYTES;
#pragma unroll
        for (int i = 0; i < 4; i++)
            cp16(sA + dst0 + i * (32 * 128), baseA + (size_t)i * 32 * ROW_B + off);
#pragma unroll
        for (int i = 0; i < 4; i++)
            cp16(sB + dst0 + i * (32 * 128), baseW + (size_t)i * 32 * ROW_B + off);
    };

    auto load_frags = [&](uint32_t (&af)[2][4], uint32_t (&bfr)[4][4],
                          uint32_t sA, uint32_t sB, int ks) {
#pragma unroll
        for (int im = 0; im < 2; im++)
            ldsm_x4(af[im], sA + SWZ((a_row + im * 16) * 128 + ks * 32 + a_ext));
#pragma unroll
        for (int jn = 0; jn < 4; jn++)
            ldsm_x4(bfr[jn], sB + SWZ((b_row + jn * 16) * 128 + ks * 32 + b_ext));
    };
    auto do_mmas = [&](const uint32_t (&af)[2][4], const uint32_t (&bfr)[4][4]) {
#pragma unroll
        for (int im = 0; im < 2; im++)
#pragma unroll
            for (int jn = 0; jn < 4; jn++) {
                mma_f16(acc[im][2 * jn + 0], af[im], bfr[jn][0], bfr[jn][1]);
                mma_f16(acc[im][2 * jn + 1], af[im], bfr[jn][2], bfr[jn][3]);
            }
    };

    // ---- prologue ----
    load_stage(0, 0); CP_COMMIT();
    load_stage(1, 1); CP_COMMIT();

    // ---- main loop: double-buffered fragments across ks ----
    int slot = 0, nslot = 2;
    uint32_t af[2][2][4], bfr[2][4][4];
    for (int kc = 0; kc < NKC; kc++) {
        CP_WAIT1();
        __syncthreads();

        uint32_t sA = sb + slot * STG;
        uint32_t sB = sA + A_BYTES;

        load_frags(af[0], bfr[0], sA, sB, 0);          // ks=0 frags right after barrier

        int nkc = kc + STAGES - 1;                      // prefetch overlaps ks=0 LDS latency
        if (nkc < NKC) load_stage(nslot, nkc);
        CP_COMMIT();

#pragma unroll
        for (int ks = 0; ks < 4; ks++) {
            if (ks < 3) load_frags(af[(ks + 1) & 1], bfr[(ks + 1) & 1], sA, sB, ks + 1);
            do_mmas(af[ks & 1], bfr[ks & 1]);
        }

        slot = (slot == STAGES - 1) ? 0 : slot + 1;
        nslot = (nslot == STAGES - 1) ? 0 : nslot + 1;
    }

    // ---- epilogue: y = sign(d) * |d|^(1/a) ----
    float a = alpha[0];
    bool fast = (a == 0.5f);
    float inv = 1.0f / a;
    const int er = m0 + warp_m * 32 + (lane >> 2);
    const int ec = n0 + warp_n * 64 + (lane & 3) * 2;
#pragma unroll
    for (int im = 0; im < 2; im++) {
#pragma unroll
        for (int in = 0; in < 8; in++) {
            float d0 = acc[im][in][0], d1 = acc[im][in][1];
            float d2 = acc[im][in][2], d3 = acc[im][in][3];
            float2 v01, v23;
            if (fast) {
                v01.x = d0 * fabsf(d0); v01.y = d1 * fabsf(d1);
                v23.x = d2 * fabsf(d2); v23.y = d3 * fabsf(d3);
            } else {
                v01.x = copysignf(powf(fabsf(d0), inv), d0);
                v01.y = copysignf(powf(fabsf(d1), inv), d1);
                v23.x = copysignf(powf(fabsf(d2), inv), d2);
                v23.y = copysignf(powf(fabsf(d3), inv), d3);
            }
            int jn = in >> 1, b = in & 1;
            int row = er + im * 16;
            int col = ec + jn * 16 + b * 8;
            *reinterpret_cast<float2*>(out + (size_t)row * OUT_F + col) = v01;
            *reinterpret_cast<float2*>(out + (size_t)(row + 8) * OUT_F + col) = v23;
        }
    }
}

// ===================== launch =====================
extern "C" void kernel_launch(void* const* d_in, const int* in_sizes, int n_in,
                              void* d_out, int out_size) {
    const float* x = nullptr;
    const float* cent = nullptr;
    const float* alpha = nullptr;
    const int*   wq = nullptr;
    for (int i = 0; i < n_in; i++) {
        long s = in_sizes[i];
        if      (s == (long)BATCH * IN_F) x     = (const float*)d_in[i];
        else if (s == 16)                 cent  = (const float*)d_in[i];
        else if (s == 1)                  alpha = (const float*)d_in[i];
        else if (s == (long)OUT_F * IN_F) wq    = (const int*)d_in[i];
    }

    cudaFuncSetAttribute(gemm_kernel, cudaFuncAttributeMaxDynamicSharedMemorySize, SMEM_TOTAL);

    convert_kernel<<<XB + WB, 256>>>(x, wq, cent, alpha);
    gemm_kernel<<<(BATCH / BM) * NB_PER_M, NTHR, SMEM_TOTAL>>>((float*)d_out, alpha);
}

// round 14
// speedup vs baseline: 6.3853x; 1.0125x over previous
#include <cuda_runtime.h>
#include <cuda_fp16.h>
#include <cstdint>
#include <cstddef>

// ===================== problem dims =====================
static constexpr int BATCH = 16384;
static constexpr int IN_F  = 2048;
static constexpr int OUT_F = 2048;

// C = A . W   single fp16 x fp16 GEMM, fp32 accum.  y = signed_pow(d, 1/a) epilogue.

// ===================== device scratch =====================
__device__ __half g_A[(size_t)BATCH * IN_F];   // 64 MiB
__device__ __half g_W[(size_t)OUT_F * IN_F];   //  8 MiB

// ===================== helpers =====================
__device__ __forceinline__ uint32_t smem_u32(const void* p) {
    uint32_t a;
    asm("{ .reg .u64 t; cvta.to.shared.u64 t, %1; cvt.u32.u64 %0, t; }" : "=r"(a) : "l"(p));
    return a;
}
__device__ __forceinline__ void cp16(uint32_t smem_dst, const void* gmem_src) {
    asm volatile("cp.async.cg.shared.global [%0], [%1], 16;" :: "r"(smem_dst), "l"(gmem_src));
}
// arrive on mbarrier when ALL prior cp.async of this thread complete (no group needed)
__device__ __forceinline__ void cp_arrive(uint32_t mbar) {
    asm volatile("cp.async.mbarrier.arrive.noinc.shared::cta.b64 [%0];" :: "r"(mbar) : "memory");
}
#define MBAR_INIT(addr, cnt) \
    asm volatile("mbarrier.init.shared.b64 [%0], %1;" :: "r"(addr), "r"(cnt) : "memory")
#define MBAR_ARRIVE(addr) \
    asm volatile("mbarrier.arrive.shared.b64 _, [%0];" :: "r"(addr) : "memory")
#define MBAR_WAIT(addr, ph) do {                                                     \
    uint32_t _m = (addr), _p = (ph), _d;                                             \
    asm volatile("{\n\t.reg .pred p;\n\t"                                            \
        "mbarrier.try_wait.parity.acquire.cta.shared::cta.b64 p, [%1], %2;\n\t"      \
        "selp.b32 %0, 1, 0, p;\n\t}"                                                 \
        : "=r"(_d) : "r"(_m), "r"(_p) : "memory");                                   \
    if (!_d) {                                                                       \
        asm volatile("{\n\t.reg .pred P1;\n\t"                                       \
            "WL%=:\n\t"                                                              \
            "mbarrier.try_wait.parity.acquire.cta.shared::cta.b64 P1, [%0], %1, 0x989680;\n\t" \
            "@P1 bra.uni WD%=;\n\t"                                                  \
            "bra.uni WL%=;\n\t"                                                      \
            "WD%=:\n\t}"                                                             \
            :: "r"(_m), "r"(_p) : "memory");                                         \
    }                                                                                \
} while (0)

__device__ __forceinline__ void ldsm_x4(uint32_t (&r)[4], uint32_t addr) {
    asm volatile("ldmatrix.sync.aligned.m8n8.x4.shared.b16 {%0,%1,%2,%3}, [%4];"
                 : "=r"(r[0]), "=r"(r[1]), "=r"(r[2]), "=r"(r[3]) : "r"(addr));
}
__device__ __forceinline__ void mma_f16(float (&d)[4], const uint32_t (&a)[4],
                                        uint32_t b0, uint32_t b1) {
    asm volatile(
        "mma.sync.aligned.m16n8k16.row.col.f32.f16.f16.f32 "
        "{%0,%1,%2,%3}, {%4,%5,%6,%7}, {%8,%9}, {%0,%1,%2,%3};"
        : "+f"(d[0]), "+f"(d[1]), "+f"(d[2]), "+f"(d[3])
        : "r"(a[0]), "r"(a[1]), "r"(a[2]), "r"(a[3]), "r"(b0), "r"(b1));
}
__device__ __forceinline__ float fast_sqrt(float x) {
    float r;
    asm("sqrt.approx.f32 %0, %1;" : "=f"(r) : "f"(x));
    return r;
}

// SW128 swizzle (Swizzle<3,4,3>) — tile bases must be 1024B aligned
#define SWZ(o) ((o) ^ (((o) >> 3) & 0x70))

// ===================== merged conversion kernel =====================
static constexpr int XB = (BATCH * IN_F / 4) / 256;   // 32768 blocks
static constexpr int WB = (OUT_F * IN_F / 4) / 256;   //  4096 blocks

__global__ void convert_kernel(const float* __restrict__ x,
                               const int* __restrict__ wq,
                               const float* __restrict__ cent,
                               const float* __restrict__ alpha) {
    int bid = blockIdx.x;
    if (bid < XB) {
        size_t i = (size_t)bid * 256 + threadIdx.x;        // float4 index
        float a = alpha[0];
        bool fast = (a == 0.5f);
        float4 v = reinterpret_cast<const float4*>(x)[i];
        float s[4] = {v.x, v.y, v.z, v.w};
        union { __half h[4]; uint2 u; } H;
#pragma unroll
        for (int k = 0; k < 4; k++) {
            float t  = s[k];
            float at = fabsf(t);
            float p  = fast ? fast_sqrt(at) : powf(at, a);
            H.h[k] = __float2half(copysignf(p, t));
        }
        reinterpret_cast<uint2*>(g_A)[i] = H.u;
    } else {
        __shared__ float c[16];
        if (threadIdx.x < 16) c[threadIdx.x] = cent[threadIdx.x];
        __syncthreads();
        size_t i = (size_t)(bid - XB) * 256 + threadIdx.x; // int4 index
        int4 q = reinterpret_cast<const int4*>(wq)[i];
        union { __half h[4]; uint2 u; } H;
        H.h[0] = __float2half(c[q.x & 15]);
        H.h[1] = __float2half(c[q.y & 15]);
        H.h[2] = __float2half(c[q.z & 15]);
        H.h[3] = __float2half(c[q.w & 15]);
        reinterpret_cast<uint2*>(g_W)[i] = H.u;
    }
}

// ===================== GEMM kernel (fp16 mma.sync, mbarrier pipeline, 2 CTA/SM) ============
static constexpr int BM = 128;
static constexpr int BN = 128;
static constexpr int STAGES = 3;
static constexpr int A_BYTES = BM * 128;          // 16 KiB (128B per row per kc)
static constexpr int B_BYTES = BN * 128;          // 16 KiB
static constexpr int STG = A_BYTES + B_BYTES;     // 32 KiB
static constexpr int MB_OFF = STAGES * STG;       // mbarriers after stages
static constexpr int SMEM_TOTAL = MB_OFF + 64;    // 96 KiB + mbar block
static constexpr int NKC = 32;                    // K=2048 fp16, 64 elems (128B) per kc
static constexpr int NTHR = 256;                  // 8 warps: 4(m) x 2(n), 32x64 warp tile
static constexpr int NB_PER_M = OUT_F / BN;       // 16 n-blocks
static constexpr int ROW_B = IN_F * 2;            // 4096 B (both A and W)

__global__ void __launch_bounds__(NTHR, 2)
gemm_kernel(float* __restrict__ out, const float* __restrict__ alpha) {
    extern __shared__ char smem_raw[];
    uint32_t sb = smem_u32(smem_raw);
    // mbarriers: full[s] @ MB_OFF + 8s, empty[s] @ MB_OFF + 24 + 8s
    const uint32_t mb_full  = sb + MB_OFF;
    const uint32_t mb_empty = sb + MB_OFF + 24;

    const int tid = threadIdx.x;
    const int wid = tid >> 5, lane = tid & 31;
    const int warp_m = wid & 3, warp_n = wid >> 2;          // 4 x 2 warps
    const int mb = blockIdx.x >> 4, nb = blockIdx.x & 15;   // n-minor: L2 A reuse
    const int m0 = mb * BM, n0 = nb * BN;

    if (tid == 0) {
#pragma unroll
        for (int s = 0; s < STAGES; s++) {
            MBAR_INIT(mb_full + 8 * s, NTHR);   // 256 cp.async-noinc arrivals
            MBAR_INIT(mb_empty + 8 * s, NTHR);  // 256 consumer arrivals
        }
    }
    __syncthreads();   // one-time: mbarrier init visible

    // cp.async base pointers
    const int ld_row = tid >> 3, ld_col = tid & 7;
    const char* baseA = (const char*)g_A + (size_t)(m0 + ld_row) * ROW_B + ld_col * 16;
    const char* baseW = (const char*)g_W + (size_t)(n0 + ld_row) * ROW_B + ld_col * 16;
    const uint32_t dst0 = SWZ(ld_row * 128 + ld_col * 16);

    // ---- ldmatrix per-lane smem offsets (within a stage) ----
    const int a_row  = warp_m * 32 + (lane & 15);
    const int a_ext  = (lane >> 4) * 16;
    const int b_row  = warp_n * 64 + (lane & 7) + ((lane >> 4) << 3);
    const int b_ext  = ((lane >> 3) & 1) * 16;

    float acc[2][8][4];
#pragma unroll
    for (int im = 0; im < 2; im++)
#pragma unroll
        for (int in = 0; in < 8; in++)
#pragma unroll
            for (int r = 0; r < 4; r++) acc[im][in][r] = 0.0f;

    auto fill_stage = [&](int slot, int kc) {
        int off = kc * 128;
        uint32_t sA = sb + slot * STG;
        uint32_t sB = sA + A_BYTES;
#pragma unroll
        for (int i = 0; i < 4; i++)
            cp16(sA + dst0 + i * (32 * 128), baseA + (size_t)i * 32 * ROW_B + off);
#pragma unroll
        for (int i = 0; i < 4; i++)
            cp16(sB + dst0 + i * (32 * 128), baseW + (size_t)i * 32 * ROW_B + off);
        cp_arrive(mb_full + 8 * slot);
    };

    auto load_frags = [&](uint32_t (&af)[2][4], uint32_t (&bfr)[4][4],
                          uint32_t sA, uint32_t sB, int ks) {
#pragma unroll
        for (int im = 0; im < 2; im++)
            ldsm_x4(af[im], sA + SWZ((a_row + im * 16) * 128 + ks * 32 + a_ext));
#pragma unroll
        for (int jn = 0; jn < 4; jn++)
            ldsm_x4(bfr[jn], sB + SWZ((b_row + jn * 16) * 128 + ks * 32 + b_ext));
    };
    auto do_mmas = [&](const uint32_t (&af)[2][4], const uint32_t (&bfr)[4][4]) {
#pragma unroll
        for (int im = 0; im < 2; im++)
#pragma unroll
            for (int jn = 0; jn < 4; jn++) {
                mma_f16(acc[im][2 * jn + 0], af[im], bfr[jn][0], bfr[jn][1]);
                mma_f16(acc[im][2 * jn + 1], af[im], bfr[jn][2], bfr[jn][3]);
            }
    };

    // cursors: consumer (stage, phase) = (0,0); producer = (0,1) -> first empty-waits pass
    int cs = 0, cph = 0;
    int ps = 0, pph = 1;

    // ---- prologue: fill stages 0,1 (empty-wait passes immediately) ----
#pragma unroll
    for (int s = 0; s < STAGES - 1; s++) {
        MBAR_WAIT(mb_empty + 8 * ps, pph);
        fill_stage(ps, s);
        if (++ps == STAGES) { ps = 0; pph ^= 1; }
    }

    // ---- main loop: no CTA-wide barrier; warps drift up to 1 kc apart ----
    uint32_t af[2][2][4], bfr[2][4][4];
    for (int kc = 0; kc < NKC; kc++) {
        MBAR_WAIT(mb_full + 8 * cs, cph);            // stage kc data ready (acquire)

        uint32_t sA = sb + cs * STG;
        uint32_t sB = sA + A_BYTES;

        load_frags(af[0], bfr[0], sA, sB, 0);        // ks=0 frags immediately

        int nkc = kc + STAGES - 1;                   // refill runs under ks=0 LDS latency
        if (nkc < NKC) {
            MBAR_WAIT(mb_empty + 8 * ps, pph);
            fill_stage(ps, nkc);
            if (++ps == STAGES) { ps = 0; pph ^= 1; }
        }

        load_frags(af[1], bfr[1], sA, sB, 1);
        do_mmas(af[0], bfr[0]);
        load_frags(af[0], bfr[0], sA, sB, 2);
        do_mmas(af[1], bfr[1]);
        load_frags(af[1], bfr[1], sA, sB, 3);
        MBAR_ARRIVE(mb_empty + 8 * cs);              // all reads of stage issued (release)
        do_mmas(af[0], bfr[0]);
        do_mmas(af[1], bfr[1]);

        if (++cs == STAGES) { cs = 0; cph ^= 1; }
    }

    // ---- epilogue: y = sign(d) * |d|^(1/a) ----
    float a = alpha[0];
    bool fast = (a == 0.5f);
    float inv = 1.0f / a;
    const int er = m0 + warp_m * 32 + (lane >> 2);
    const int ec = n0 + warp_n * 64 + (lane & 3) * 2;
#pragma unroll
    for (int im = 0; im < 2; im++) {
#pragma unroll
        for (int in = 0; in < 8; in++) {
            float d0 = acc[im][in][0], d1 = acc[im][in][1];
            float d2 = acc[im][in][2], d3 = acc[im][in][3];
            float2 v01, v23;
            if (fast) {
                v01.x = d0 * fabsf(d0); v01.y = d1 * fabsf(d1);
                v23.x = d2 * fabsf(d2); v23.y = d3 * fabsf(d3);
            } else {
                v01.x = copysignf(powf(fabsf(d0), inv), d0);
                v01.y = copysignf(powf(fabsf(d1), inv), d1);
                v23.x = copysignf(powf(fabsf(d2), inv), d2);
                v23.y = copysignf(powf(fabsf(d3), inv), d3);
            }
            int jn = in >> 1, b = in & 1;
            int row = er + im * 16;
            int col = ec + jn * 16 + b * 8;
            *reinterpret_cast<float2*>(out + (size_t)row * OUT_F + col) = v01;
            *reinterpret_cast<float2*>(out + (size_t)(row + 8) * OUT_F + col) = v23;
        }
    }
}

// ===================== launch =====================
extern "C" void kernel_launch(void* const* d_in, const int* in_sizes, int n_in,
                              void* d_out, int out_size) {
    const float* x = nullptr;
    const float* cent = nullptr;
    const float* alpha = nullptr;
    const int*   wq = nullptr;
    for (int i = 0; i < n_in; i++) {
        long s = in_sizes[i];
        if      (s == (long)BATCH * IN_F) x     = (const float*)d_in[i];
        else if (s == 16)                 cent  = (const float*)d_in[i];
        else if (s == 1)                  alpha = (const float*)d_in[i];
        else if (s == (long)OUT_F * IN_F) wq    = (const int*)d_in[i];
    }

    cudaFuncSetAttribute(gemm_kernel, cudaFuncAttributeMaxDynamicSharedMemorySize, SMEM_TOTAL);

    convert_kernel<<<XB + WB, 256>>>(x, wq, cent, alpha);
    gemm_kernel<<<(BATCH / BM) * NB_PER_M, NTHR, SMEM_TOTAL>>>((float*)d_out, alpha);
}